// round 10
// baseline (speedup 1.0000x reference)
#include <cuda_runtime.h>

#define N_NODES 200000
#define C_IN 5
#define T_BLK 256

// Scratch in __device__ globals (zero-initialized at module load).
// g_cnt is re-zeroed in the prep epilogue each call; the ticket counters
// self-reset at the end of each kernel, so every call sees zeros.
__device__ int    g_cnt[N_NODES];     // in-degree (dst counts), excl. self-loop
__device__ float2 g_hs[N_NODES];      // (x @ W) * dinv
__device__ float  g_dinv[N_NODES];    // rsqrt(deg)
__device__ float2 g_acc[N_NODES];     // sum of hs[src] per dst (init = self-loop)
__device__ unsigned g_ctr1, g_done1, g_ctr2, g_done2;

__device__ __forceinline__ void red_add_v2(float2* addr, float a, float b) {
    asm volatile("red.global.add.v2.f32 [%0], {%1, %2};"
                 :: "l"(addr), "f"(a), "f"(b)
                 : "memory");
}

__device__ __forceinline__ int4 ldg_cs_int4(const int4* p) {
    int4 v;
    asm volatile("ld.global.cs.v4.s32 {%0,%1,%2,%3}, [%4];"
                 : "=r"(v.x), "=r"(v.y), "=r"(v.z), "=r"(v.w) : "l"(p));
    return v;
}

__device__ __forceinline__ float2 ldg_ca_f2(const float2* p) {
    float2 v;
    asm volatile("ld.global.ca.v2.f32 {%0,%1}, [%2];"
                 : "=f"(v.x), "=f"(v.y) : "l"(p));
    return v;
}

// ---- Kernel A: edge count + (ticket-gated) prep epilogue ----
__global__ void __launch_bounds__(T_BLK) k_count_prep(const int4* __restrict__ dst4, int E4,
                                                      const float* __restrict__ x,
                                                      const float* __restrict__ W,
                                                      int n, int S) {
    int i = blockIdx.x * blockDim.x + threadIdx.x;
    if (i < E4) {
        int4 d = ldg_cs_int4(dst4 + i);
        atomicAdd(&g_cnt[d.x], 1);
        atomicAdd(&g_cnt[d.y], 1);
        atomicAdd(&g_cnt[d.z], 1);
        atomicAdd(&g_cnt[d.w], 1);
    }
    __threadfence();
    __syncthreads();
    __shared__ unsigned tkt;
    if (threadIdx.x == 0) tkt = atomicAdd(&g_ctr1, 1u);
    __syncthreads();
    unsigned grid = gridDim.x;
    unsigned t = tkt;
    if (t >= grid - (unsigned)S) {
        // Last S ticket-holders run the prep epilogue once all counts are in.
        if (threadIdx.x == 0) {
            while (*(volatile unsigned*)&g_ctr1 < grid) {}
            __threadfence();
        }
        __syncthreads();
        int epi = (int)(t - (grid - (unsigned)S));
        int stride = S * T_BLK;
        for (int j = epi * T_BLK + threadIdx.x; j < n; j += stride) {
            int c = g_cnt[j];
            g_cnt[j] = 0;                             // re-arm for next call
            float dinv = rsqrtf((float)(c + 1));      // +1 self-loop
            const float* xr = x + (size_t)j * C_IN;
            float x0 = xr[0], x1 = xr[1], x2 = xr[2], x3 = xr[3], x4 = xr[4];
            float h0 = x0 * W[0] + x1 * W[2] + x2 * W[4] + x3 * W[6] + x4 * W[8];
            float h1 = x0 * W[1] + x1 * W[3] + x2 * W[5] + x3 * W[7] + x4 * W[9];
            float2 hs = make_float2(h0 * dinv, h1 * dinv);
            g_hs[j] = hs;
            g_dinv[j] = dinv;
            g_acc[j] = hs;   // self-loop term (dinv[dst] applied at finalize)
        }
        __threadfence();
        __syncthreads();
        if (threadIdx.x == 0) {
            unsigned d = atomicAdd(&g_done1, 1u);
            if (d == (unsigned)S - 1u) { g_ctr1 = 0; __threadfence(); g_done1 = 0; }
        }
    }
    cudaTriggerProgrammaticLaunchCompletion();
}

// ---- Kernel B: edge scatter + (ticket-gated) finalize epilogue ----
__global__ void __launch_bounds__(T_BLK) k_scatter_final(const int4* __restrict__ src4,
                                                         const int4* __restrict__ dst4,
                                                         int E4,
                                                         const float* __restrict__ x,
                                                         const float* __restrict__ b,
                                                         float* __restrict__ out,
                                                         int n, int S) {
    int i = blockIdx.x * blockDim.x + threadIdx.x;
    int4 s, d;
    bool active = (i < E4);
    if (active) {               // prefetch indices (inputs, independent of kernel A)
        s = ldg_cs_int4(src4 + i);
        d = ldg_cs_int4(dst4 + i);
    }
    cudaGridDependencySynchronize();
    if (active) {
        float2 a  = ldg_ca_f2(&g_hs[s.x]);
        float2 bb = ldg_ca_f2(&g_hs[s.y]);
        float2 c  = ldg_ca_f2(&g_hs[s.z]);
        float2 e  = ldg_ca_f2(&g_hs[s.w]);
        red_add_v2(&g_acc[d.x], a.x, a.y);
        red_add_v2(&g_acc[d.y], bb.x, bb.y);
        red_add_v2(&g_acc[d.z], c.x, c.y);
        red_add_v2(&g_acc[d.w], e.x, e.y);
    }
    __threadfence();
    __syncthreads();
    __shared__ unsigned tkt;
    if (threadIdx.x == 0) tkt = atomicAdd(&g_ctr2, 1u);
    __syncthreads();
    unsigned grid = gridDim.x;
    unsigned t = tkt;
    if (t >= grid - (unsigned)S) {
        if (threadIdx.x == 0) {
            while (*(volatile unsigned*)&g_ctr2 < grid) {}
            __threadfence();
        }
        __syncthreads();
        float b0 = b[0], b1 = b[1];
        int epi = (int)(t - (grid - (unsigned)S));
        int stride = S * T_BLK;
        for (int j = epi * T_BLK + threadIdx.x; j < n; j += stride) {
            float2 a = g_acc[j];
            float dinv = g_dinv[j];
            float acc0 = (a.x * dinv + b0) * 0.01f;
            float acc1 = (a.y * dinv + b1) * 0.01f;
            const float* xr = x + (size_t)j * C_IN;
            float v0 = fminf(fmaxf(xr[2] + acc0, -0.1f), 0.1f);
            float v1 = fminf(fmaxf(xr[3] + acc1, -0.1f), 0.1f);
            float p0 = fminf(fmaxf(xr[0] + v0, -1.0f), 1.0f);
            float p1 = fminf(fmaxf(xr[1] + v1, -1.0f), 1.0f);
            float* orow = out + (size_t)j * C_IN;
            orow[0] = p0;
            orow[1] = p1;
            orow[2] = v0;
            orow[3] = v1;
            orow[4] = xr[4];
        }
        __syncthreads();
        if (threadIdx.x == 0) {
            unsigned dd = atomicAdd(&g_done2, 1u);
            if (dd == (unsigned)S - 1u) { g_ctr2 = 0; __threadfence(); g_done2 = 0; }
        }
    }
}

template <typename... Args>
static inline void launch_pdl(void (*kern)(Args...), int grid, int block,
                              Args... args) {
    cudaLaunchConfig_t cfg = {};
    cfg.gridDim = dim3(grid);
    cfg.blockDim = dim3(block);
    cudaLaunchAttribute attr[1];
    attr[0].id = cudaLaunchAttributeProgrammaticStreamSerialization;
    attr[0].val.programmaticStreamSerializationAllowed = 1;
    cfg.attrs = attr;
    cfg.numAttrs = 1;
    cudaLaunchKernelEx(&cfg, kern, args...);
}

extern "C" void kernel_launch(void* const* d_in, const int* in_sizes, int n_in,
                              void* d_out, int out_size) {
    const float* x  = (const float*)d_in[0];   // [N,5]
    const int*   ei = (const int*)d_in[1];     // [2,E]: src row then dst row
    const float* W  = (const float*)d_in[2];   // [5,2]
    const float* b  = (const float*)d_in[3];   // [2]
    float* out = (float*)d_out;

    int n = in_sizes[0] / C_IN;     // 200000
    int E = in_sizes[1] / 2;        // 12800000 (divisible by 4)
    const int* src = ei;
    const int* dst = ei + E;
    int E4 = E / 4;

    int gE4 = (E4 + T_BLK - 1) / T_BLK;         // 12500
    int S   = (n + T_BLK - 1) / T_BLK;          // 782 epilogue blocks

    k_count_prep<<<gE4, T_BLK>>>((const int4*)dst, E4, x, W, n, S);
    launch_pdl(k_scatter_final, gE4, T_BLK,
               (const int4*)src, (const int4*)dst, E4, x, b, out, n, S);
}

// round 11
// speedup vs baseline: 1.3482x; 1.3482x over previous
#include <cuda_runtime.h>

#define N_NODES 200000
#define C_IN 5

// Scratch in __device__ globals (zero-initialized at module load; k_final
// re-zeroes g_cnt each call so every invocation sees zeros -- deterministic).
__device__ int    g_cnt[N_NODES];     // in-degree (dst counts), excl. self-loop
__device__ float2 g_hs[N_NODES];      // (x @ W) * dinv
__device__ float  g_dinv[N_NODES];    // rsqrt(deg)
__device__ float2 g_acc[N_NODES];     // sum of hs[src] per dst (init = self-loop term)

__device__ __forceinline__ void red_add_v2(float2* addr, float a, float b) {
    asm volatile("red.global.add.v2.f32 [%0], {%1, %2};"
                 :: "l"(addr), "f"(a), "f"(b)
                 : "memory");
}

// Streaming (evict-first) int4 load: don't pollute L1 with one-touch index data.
__device__ __forceinline__ int4 ldg_cs_int4(const int4* p) {
    int4 v;
    asm volatile("ld.global.cs.v4.s32 {%0,%1,%2,%3}, [%4];"
                 : "=r"(v.x), "=r"(v.y), "=r"(v.z), "=r"(v.w) : "l"(p));
    return v;
}

// Cache-all gather of float2 (keep hs table resident in L1).
__device__ __forceinline__ float2 ldg_ca_f2(const float2* p) {
    float2 v;
    asm volatile("ld.global.ca.v2.f32 {%0,%1}, [%2];"
                 : "=f"(v.x), "=f"(v.y) : "l"(p));
    return v;
}

// 4 edges/thread; 1 random RED per edge.
__global__ void __launch_bounds__(256) k_count(const int4* __restrict__ dst4, int E4) {
    int i = blockIdx.x * blockDim.x + threadIdx.x;
    if (i < E4) {
        int4 d = ldg_cs_int4(dst4 + i);
        atomicAdd(&g_cnt[d.x], 1);
        atomicAdd(&g_cnt[d.y], 1);
        atomicAdd(&g_cnt[d.z], 1);
        atomicAdd(&g_cnt[d.w], 1);
    }
    cudaTriggerProgrammaticLaunchCompletion();
}

// PDL-gated on k_count; x@W computed PRE-sync (independent of counts).
__global__ void k_prep(const float* __restrict__ x,
                       const float* __restrict__ W,
                       int n) {
    int i = blockIdx.x * blockDim.x + threadIdx.x;
    float h0 = 0.0f, h1 = 0.0f;
    if (i < n) {
        const float* xr = x + (size_t)i * C_IN;
        float x0 = xr[0], x1 = xr[1], x2 = xr[2], x3 = xr[3], x4 = xr[4];
        h0 = x0 * W[0] + x1 * W[2] + x2 * W[4] + x3 * W[6] + x4 * W[8];
        h1 = x0 * W[1] + x1 * W[3] + x2 * W[5] + x3 * W[7] + x4 * W[9];
    }
    cudaGridDependencySynchronize();
    if (i < n) {
        float dinv = rsqrtf((float)(g_cnt[i] + 1));   // +1 self-loop
        float2 hs = make_float2(h0 * dinv, h1 * dinv);
        g_hs[i] = hs;
        g_dinv[i] = dinv;
        g_acc[i] = hs;   // self-loop contribution (dinv[dst] applied at finalize)
    }
    cudaTriggerProgrammaticLaunchCompletion();
}

// PDL-gated on k_prep; edge indices prefetched PRE-sync (pure inputs).
__global__ void __launch_bounds__(256) k_scatter(const int4* __restrict__ src4,
                                                 const int4* __restrict__ dst4,
                                                 int E4) {
    int i = blockIdx.x * blockDim.x + threadIdx.x;
    int4 s, d;
    bool active = (i < E4);
    if (active) {
        s = ldg_cs_int4(src4 + i);
        d = ldg_cs_int4(dst4 + i);
    }
    cudaGridDependencySynchronize();
    if (active) {
        float2 a  = ldg_ca_f2(&g_hs[s.x]);
        float2 bb = ldg_ca_f2(&g_hs[s.y]);
        float2 c  = ldg_ca_f2(&g_hs[s.z]);
        float2 e  = ldg_ca_f2(&g_hs[s.w]);
        red_add_v2(&g_acc[d.x], a.x, a.y);
        red_add_v2(&g_acc[d.y], bb.x, bb.y);
        red_add_v2(&g_acc[d.z], c.x, c.y);
        red_add_v2(&g_acc[d.w], e.x, e.y);
    }
    cudaTriggerProgrammaticLaunchCompletion();
}

// PDL-gated on k_scatter; x/b loaded PRE-sync (pure inputs).
__global__ void k_final(const float* __restrict__ x,
                        const float* __restrict__ b,
                        float* __restrict__ out,
                        int n) {
    int i = blockIdx.x * blockDim.x + threadIdx.x;
    float x0 = 0, x1 = 0, x2 = 0, x3 = 0, x4 = 0, b0 = 0, b1 = 0;
    if (i < n) {
        const float* xr = x + (size_t)i * C_IN;
        x0 = xr[0]; x1 = xr[1]; x2 = xr[2]; x3 = xr[3]; x4 = xr[4];
        b0 = b[0]; b1 = b[1];
    }
    cudaGridDependencySynchronize();
    if (i >= n) return;
    float2 a = g_acc[i];
    float dinv = g_dinv[i];
    g_cnt[i] = 0;                      // re-arm counts for the next call
    float acc0 = (a.x * dinv + b0) * 0.01f;
    float acc1 = (a.y * dinv + b1) * 0.01f;
    float v0 = fminf(fmaxf(x2 + acc0, -0.1f), 0.1f);
    float v1 = fminf(fmaxf(x3 + acc1, -0.1f), 0.1f);
    float p0 = fminf(fmaxf(x0 + v0, -1.0f), 1.0f);
    float p1 = fminf(fmaxf(x1 + v1, -1.0f), 1.0f);
    float* orow = out + (size_t)i * C_IN;
    orow[0] = p0;
    orow[1] = p1;
    orow[2] = v0;
    orow[3] = v1;
    orow[4] = x4;
}

template <typename... Args>
static inline void launch_pdl(void (*kern)(Args...), int grid, int block,
                              Args... args) {
    cudaLaunchConfig_t cfg = {};
    cfg.gridDim = dim3(grid);
    cfg.blockDim = dim3(block);
    cudaLaunchAttribute attr[1];
    attr[0].id = cudaLaunchAttributeProgrammaticStreamSerialization;
    attr[0].val.programmaticStreamSerializationAllowed = 1;
    cfg.attrs = attr;
    cfg.numAttrs = 1;
    cudaLaunchKernelEx(&cfg, kern, args...);
}

extern "C" void kernel_launch(void* const* d_in, const int* in_sizes, int n_in,
                              void* d_out, int out_size) {
    const float* x  = (const float*)d_in[0];   // [N,5]
    const int*   ei = (const int*)d_in[1];     // [2,E]: src row then dst row
    const float* W  = (const float*)d_in[2];   // [5,2]
    const float* b  = (const float*)d_in[3];   // [2]
    float* out = (float*)d_out;

    int n = in_sizes[0] / C_IN;     // 200000
    int E = in_sizes[1] / 2;        // 12800000 (divisible by 4)
    const int* src = ei;
    const int* dst = ei + E;
    int E4 = E / 4;

    const int T = 256;
    int gN  = (n + T - 1) / T;
    int gE4 = (E4 + T - 1) / T;

    k_count<<<gE4, T>>>((const int4*)dst, E4);
    launch_pdl(k_prep, gN, T, x, W, n);
    launch_pdl(k_scatter, gE4, T, (const int4*)src, (const int4*)dst, E4);
    launch_pdl(k_final, gN, T, x, b, out, n);
}

// round 12
// speedup vs baseline: 1.3678x; 1.0145x over previous
#include <cuda_runtime.h>

#define N_NODES 200000
#define C_IN 5
#define T_BLK 256

// Per-node packed struct: {h0, h1, cnt(int bits), pad}. 16B aligned.
// Invariant across calls (zero-init at load, restored by k_final each call):
//   cnt field == 0, g_acc == 0 at every call entry.
__device__ float4 g_node[N_NODES];
__device__ float2 g_acc[N_NODES];    // edge-sum of h[src]*dinv[src] per dst

__device__ __forceinline__ void red_add_v2(float2* addr, float a, float b) {
    asm volatile("red.global.add.v2.f32 [%0], {%1, %2};"
                 :: "l"(addr), "f"(a), "f"(b)
                 : "memory");
}

__device__ __forceinline__ int4 ldg_cs_int4(const int4* p) {
    int4 v;
    asm volatile("ld.global.cs.v4.s32 {%0,%1,%2,%3}, [%4];"
                 : "=r"(v.x), "=r"(v.y), "=r"(v.z), "=r"(v.w) : "l"(p));
    return v;
}

// Cache-all 16B gather of the node struct.
__device__ __forceinline__ float4 ldg_ca_f4(const float4* p) {
    float4 v;
    asm volatile("ld.global.ca.v4.f32 {%0,%1,%2,%3}, [%4];"
                 : "=f"(v.x), "=f"(v.y), "=f"(v.z), "=f"(v.w) : "l"(p));
    return v;
}

// Hetero grid, h-blocks FIRST: blocks [0,gN) write h into g_node[].xy;
// blocks [gN, gN+gE4) RED in-degree into g_node[].z (disjoint bytes).
__global__ void __launch_bounds__(T_BLK) k_count_h(const int4* __restrict__ dst4, int E4,
                                                   const float* __restrict__ x,
                                                   const float* __restrict__ W,
                                                   int n, int gN) {
    if (blockIdx.x < (unsigned)gN) {
        int i = blockIdx.x * T_BLK + threadIdx.x;
        if (i < n) {
            const float* xr = x + (size_t)i * C_IN;
            float x0 = xr[0], x1 = xr[1], x2 = xr[2], x3 = xr[3], x4 = xr[4];
            float h0 = x0 * W[0] + x1 * W[2] + x2 * W[4] + x3 * W[6] + x4 * W[8];
            float h1 = x0 * W[1] + x1 * W[3] + x2 * W[5] + x3 * W[7] + x4 * W[9];
            *(float2*)&g_node[i] = make_float2(h0, h1);   // .xy only
        }
    } else {
        int i = (blockIdx.x - gN) * T_BLK + threadIdx.x;
        if (i < E4) {
            int4 d = ldg_cs_int4(dst4 + i);
            atomicAdd((int*)&g_node[d.x].z, 1);
            atomicAdd((int*)&g_node[d.y].z, 1);
            atomicAdd((int*)&g_node[d.z].z, 1);
            atomicAdd((int*)&g_node[d.w].z, 1);
        }
    }
    cudaTriggerProgrammaticLaunchCompletion();
}

// 4 edges/thread: ONE 16B struct gather per edge; dinv computed inline;
// fused v2 RED into acc[dst]. PDL-gated on k_count_h.
__global__ void __launch_bounds__(T_BLK) k_scatter(const int4* __restrict__ src4,
                                                   const int4* __restrict__ dst4,
                                                   int E4) {
    int i = blockIdx.x * blockDim.x + threadIdx.x;
    int4 s, d;
    bool active = (i < E4);
    if (active) {                 // prefetch indices (pure inputs)
        s = ldg_cs_int4(src4 + i);
        d = ldg_cs_int4(dst4 + i);
    }
    cudaGridDependencySynchronize();
    if (active) {
        float4 a = ldg_ca_f4(&g_node[s.x]);
        float4 b = ldg_ca_f4(&g_node[s.y]);
        float4 c = ldg_ca_f4(&g_node[s.z]);
        float4 e = ldg_ca_f4(&g_node[s.w]);
        float da = rsqrtf((float)(__float_as_int(a.z) + 1));
        float db = rsqrtf((float)(__float_as_int(b.z) + 1));
        float dc = rsqrtf((float)(__float_as_int(c.z) + 1));
        float de = rsqrtf((float)(__float_as_int(e.z) + 1));
        red_add_v2(&g_acc[d.x], a.x * da, a.y * da);
        red_add_v2(&g_acc[d.y], b.x * db, b.y * db);
        red_add_v2(&g_acc[d.z], c.x * dc, c.y * dc);
        red_add_v2(&g_acc[d.w], e.x * de, e.y * de);
    }
    cudaTriggerProgrammaticLaunchCompletion();
}

// Finalize: self-loop term added here; resets cnt and acc for next call.
__global__ void k_final(const float* __restrict__ x,
                        const float* __restrict__ b,
                        float* __restrict__ out,
                        int n) {
    int i = blockIdx.x * blockDim.x + threadIdx.x;
    float x0 = 0, x1 = 0, x2 = 0, x3 = 0, x4 = 0, b0 = 0, b1 = 0;
    if (i < n) {
        const float* xr = x + (size_t)i * C_IN;
        x0 = xr[0]; x1 = xr[1]; x2 = xr[2]; x3 = xr[3]; x4 = xr[4];
        b0 = b[0]; b1 = b[1];
    }
    cudaGridDependencySynchronize();
    if (i >= n) return;
    float4 nd = g_node[i];
    float2 a = g_acc[i];
    // restore invariants for the next call
    g_acc[i] = make_float2(0.0f, 0.0f);
    *(int*)&g_node[i].z = 0;
    float dinv = rsqrtf((float)(__float_as_int(nd.z) + 1));   // +1 self-loop
    // out = dinv * (edge_sum + self_loop h*dinv) + bias
    float sum0 = a.x + nd.x * dinv;
    float sum1 = a.y + nd.y * dinv;
    float acc0 = (sum0 * dinv + b0) * 0.01f;
    float acc1 = (sum1 * dinv + b1) * 0.01f;
    float v0 = fminf(fmaxf(x2 + acc0, -0.1f), 0.1f);
    float v1 = fminf(fmaxf(x3 + acc1, -0.1f), 0.1f);
    float p0 = fminf(fmaxf(x0 + v0, -1.0f), 1.0f);
    float p1 = fminf(fmaxf(x1 + v1, -1.0f), 1.0f);
    float* orow = out + (size_t)i * C_IN;
    orow[0] = p0;
    orow[1] = p1;
    orow[2] = v0;
    orow[3] = v1;
    orow[4] = x4;
}

template <typename... Args>
static inline void launch_pdl(void (*kern)(Args...), int grid, int block,
                              Args... args) {
    cudaLaunchConfig_t cfg = {};
    cfg.gridDim = dim3(grid);
    cfg.blockDim = dim3(block);
    cudaLaunchAttribute attr[1];
    attr[0].id = cudaLaunchAttributeProgrammaticStreamSerialization;
    attr[0].val.programmaticStreamSerializationAllowed = 1;
    cfg.attrs = attr;
    cfg.numAttrs = 1;
    cudaLaunchKernelEx(&cfg, kern, args...);
}

extern "C" void kernel_launch(void* const* d_in, const int* in_sizes, int n_in,
                              void* d_out, int out_size) {
    const float* x  = (const float*)d_in[0];   // [N,5]
    const int*   ei = (const int*)d_in[1];     // [2,E]: src row then dst row
    const float* W  = (const float*)d_in[2];   // [5,2]
    const float* b  = (const float*)d_in[3];   // [2]
    float* out = (float*)d_out;

    int n = in_sizes[0] / C_IN;     // 200000
    int E = in_sizes[1] / 2;        // 12800000 (divisible by 4)
    const int* src = ei;
    const int* dst = ei + E;
    int E4 = E / 4;

    int gN  = (n + T_BLK - 1) / T_BLK;
    int gE4 = (E4 + T_BLK - 1) / T_BLK;

    k_count_h<<<gN + gE4, T_BLK>>>((const int4*)dst, E4, x, W, n, gN);
    launch_pdl(k_scatter, gE4, T_BLK, (const int4*)src, (const int4*)dst, E4);
    launch_pdl(k_final, gN, T_BLK, x, b, out, n);
}